// round 16
// baseline (speedup 1.0000x reference)
#include <cuda_runtime.h>
#include <cuda_bf16.h>
#include <cuda_fp16.h>
#include <math.h>
#include <stdint.h>

// Problem constants
#define D64   64
#define HH    2
#define HD    128
#define LL    3
#define NN    50000
#define GG    128
#define EE    600000
#define NE_   300000
#define NAUG  (NN + GG)          // 50128
#define M0    (EE + 2 * NN)      // 700000
#define MM    (M0 + NAUG)        // 750128
#define NB_SCAN ((NAUG + 255) / 256)   // 196
#define NB_GEN  ((NN * 32 + 255) / 256)
#define NSTAGE (2 * LL + 1)      // 7 LN-stats stages

#define CDIV(a, b) (((a) + (b) - 1) / (b))

// ---------------- device scratch (static, no allocs) ----------------
__device__ int    g_src[MM];
__device__ int    g_dst[MM];
__device__ int    g_deg[NAUG];
__device__ int    g_rowptr[NAUG + 1];
__device__ int    g_bsum[256];
__device__ int    g_fill[NAUG];
__device__ int    g_esrc[MM];
__device__ int    g_eid[MM];
__device__ __half g_eperm[(size_t)MM * D64];     // e_aug rows in CSR order, fp16
__device__ float  g_h[NAUG * D64];
__device__ float  g_big[(size_t)NAUG * 384];     // [hn|geno | t | we]
__device__ float  g_qkvp[(size_t)NAUG * 512];    // [q | k | v | qp]
__device__ float  g_lh[NAUG * D64];
__device__ float  g_ffh[(size_t)NAUG * 256];
// per-layer precomputed weights
__device__ float  g_qpw[LL][HD * HD];
__device__ float  g_swlw[LL][HD * D64];
__device__ float  g_lw3[LL][HD * D64];
__device__ float  g_blb[LL][D64];
__device__ float  g_wcat2[LL][HD * 512];
__device__ float  g_bcat2[LL][512];
__device__ float  g_wlin2[LL][384 * D64];
__device__ float  g_blb2[LL][D64];
// LN stage buffers / misc
__device__ float  g_cntn[GG];
__device__ double g_lsum[NSTAGE * GG];
__device__ double g_lsumsq[NSTAGE * GG];
__device__ int    g_abatch[NAUG];
__device__ float  g_gsum[GG * D64];

// ---------------- setup kernels ----------------
__global__ void k_build_edges(const int* __restrict__ ei0, const int* __restrict__ ei1,
                              const int* __restrict__ batch) {
    int m = blockIdx.x * blockDim.x + threadIdx.x;
    if (m >= MM) return;
    int s, d;
    if (m < EE)               { s = ei0[m]; d = ei1[m]; }
    else if (m < EE + NN)     { int i = m - EE;          s = i;             d = batch[i] + NN; }
    else if (m < EE + 2 * NN) { int i = m - EE - NN;     s = batch[i] + NN; d = i; }
    else                      { int i = m - EE - 2 * NN; s = i;             d = i; }
    g_src[m] = s; g_dst[m] = d;
    atomicAdd(&g_deg[d], 1);
}

__global__ void k_scanA() {
    __shared__ int sh[256];
    int t = threadIdx.x;
    int i = blockIdx.x * 256 + t;
    int v = (i < NAUG) ? g_deg[i] : 0;
    sh[t] = v;
    __syncthreads();
    for (int off = 1; off < 256; off <<= 1) {
        int a = (t >= off) ? sh[t - off] : 0;
        __syncthreads();
        sh[t] += a;
        __syncthreads();
    }
    if (i < NAUG) g_rowptr[i] = sh[t] - v;
    if (t == 255) g_bsum[blockIdx.x] = sh[255];
}

__global__ void k_scanB() {
    __shared__ int sh[256];
    int t = threadIdx.x;
    int v = (t < NB_SCAN) ? g_bsum[t] : 0;
    sh[t] = v;
    __syncthreads();
    for (int off = 1; off < 256; off <<= 1) {
        int a = (t >= off) ? sh[t - off] : 0;
        __syncthreads();
        sh[t] += a;
        __syncthreads();
    }
    if (t < NB_SCAN) g_bsum[t] = sh[t] - v;
}

__global__ void k_scanC() {
    int i = blockIdx.x * 256 + threadIdx.x;
    if (i < NAUG) {
        int r = g_rowptr[i] + g_bsum[i >> 8];
        g_rowptr[i] = r;
        g_fill[i] = r;
        g_deg[i] = 0;
    }
    if (i == 0) g_rowptr[NAUG] = MM;
}

__global__ void k_scatter() {
    int m = blockIdx.x * blockDim.x + threadIdx.x;
    if (m >= MM) return;
    int pos = atomicAdd(&g_fill[g_dst[m]], 1);
    g_esrc[pos] = g_src[m];
    g_eid[pos]  = m;
}

// fused misc setup: init h, abatch, cntn, layer-0 LN1 stats (stage 0)
__global__ void k_misc(const float* __restrict__ x, const float* __restrict__ cond,
                       const int* __restrict__ batch) {
    int idx = blockIdx.x * blockDim.x + threadIdx.x;
    if (idx < NAUG * D64)
        g_h[idx] = (idx < NN * D64) ? x[idx] : cond[idx - NN * D64];
    if (idx < NAUG)
        g_abatch[idx] = (idx < NN) ? batch[idx] : (idx - NN);
    if (idx < NN)
        atomicAdd(&g_cntn[batch[idx]], 1.f);
    int w = idx >> 5, lane = idx & 31;
    if (w < NAUG) {
        const float* src = (w < NN) ? x + (size_t)w * D64 : cond + (size_t)(w - NN) * D64;
        float2 v = ((const float2*)src)[lane];
        float s = v.x + v.y, ss = v.x * v.x + v.y * v.y;
#pragma unroll
        for (int off = 16; off; off >>= 1) {
            s  += __shfl_xor_sync(0xffffffffu, s, off);
            ss += __shfl_xor_sync(0xffffffffu, ss, off);
        }
        if (lane == 0) {
            int b = (w < NN) ? batch[w] : (w - NN);
            atomicAdd(&g_lsum[b], (double)s);
            atomicAdd(&g_lsumsq[b], (double)ss);
        }
    }
}

// fused eperm build: warp per node; fp16 rows in CSR order, self-loop filled last.
__global__ void k_eperm(const float* __restrict__ edge_attr) {
    int i = (blockIdx.x * blockDim.x + threadIdx.x) >> 5;
    int lane = threadIdx.x & 31;
    if (i >= NAUG) return;
    float2 acc = {0.f, 0.f};
    float cnt = 0.f;
    int loopPos = -1;
    int e0 = g_rowptr[i], e1 = g_rowptr[i + 1];
    for (int e = e0; e < e1; e++) {
        int m = g_eid[e];
        float2 ev;
        if (m < EE) {
            ev = ((const float2*)(edge_attr + (size_t)m * D64))[lane];
            acc.x += ev.x; acc.y += ev.y;
            cnt += 1.f;
        } else if (m < M0) {
            ev = make_float2((lane == 0) ? 1.f : 0.f, 0.f);
            acc.x += ev.x;
            cnt += 1.f;
        } else {
            loopPos = e;
            continue;
        }
        ((__half2*)(g_eperm + (size_t)e * D64))[lane] = __floats2half2_rn(ev.x, ev.y);
    }
    float invc = 1.f / fmaxf(cnt, 1.f);
    if (loopPos >= 0)
        ((__half2*)(g_eperm + (size_t)loopPos * D64))[lane] =
            __floats2half2_rn(acc.x * invc, acc.y * invc);
}

// ---------------- batched weight prep ----------------
#define P1_PER (128 * 128 + 128 * 64 + 128 * 64 + 64)
__global__ void k_prep1(const float* __restrict__ qw_all, const float* __restrict__ ew_all,
                        const float* __restrict__ sw_all, const float* __restrict__ lw_all,
                        const float* __restrict__ sb_all, const float* __restrict__ lb_all) {
    int idx = blockIdx.x * blockDim.x + threadIdx.x;
    int l = idx / P1_PER, j = idx % P1_PER;
    if (l >= LL) return;
    const float* qw = qw_all + (size_t)l * HD * HD;
    const float* ew = ew_all + (size_t)l * D64 * HD;
    const float* sw = sw_all + (size_t)l * HD * HD;
    const float* lw = lw_all + (size_t)l * HD * D64;
    const float* sb = sb_all + (size_t)l * HD;
    const float* lb = lb_all + (size_t)l * D64;
    if (j < 128 * 128) {
        int xx = j >> 7, o = j & 127;
        int h = o >> 6, c = o & 63;
        float a = 0.f;
        for (int d = 0; d < 64; d++) a += qw[xx * HD + h * 64 + d] * ew[c * HD + h * 64 + d];
        g_qpw[l][j] = a;
    } else if (j < 128 * 128 + 128 * 64) {
        int jj = j - 128 * 128;
        int r = jj >> 6, u = jj & 63;
        float a = 0.f;
        for (int k2 = 0; k2 < 128; k2++) a += sw[r * HD + k2] * lw[k2 * D64 + u];
        g_swlw[l][jj] = a;
    } else if (j < 128 * 128 + 2 * 128 * 64) {
        int jj = j - 128 * 128 - 128 * 64;
        int r = jj >> 6, u = jj & 63;
        int h = r >> 6, c = r & 63;
        float a = 0.f;
        for (int o2 = 0; o2 < 64; o2++)
            a += ew[c * HD + h * 64 + o2] * lw[(h * 64 + o2) * D64 + u];
        g_lw3[l][jj] = a;
    } else {
        int o = j - 128 * 128 - 2 * 128 * 64;
        float a = lb[o];
        for (int k2 = 0; k2 < 128; k2++) a += sb[k2] * lw[k2 * D64 + o];
        g_blb[l][o] = a;
    }
}

__device__ __forceinline__ float wcat_row(const float* qw, const float* kw,
                                          const float* vw, const float* qpw,
                                          int r, int c) {
    if (c < 128) return qw[r * HD + c];
    if (c < 256) return kw[r * HD + c - 128];
    if (c < 384) return vw[r * HD + c - 256];
    return qpw[r * HD + c - 384];
}

#define P2_PER (128 * 512 + 384 * 64 + 512 + 64)
__global__ void k_prep2(const float* __restrict__ qw_all, const float* __restrict__ kw_all,
                        const float* __restrict__ vw_all, const float* __restrict__ ew_all,
                        const float* __restrict__ gw_all, const float* __restrict__ gb_all,
                        const float* __restrict__ qb_all, const float* __restrict__ kb_all,
                        const float* __restrict__ vb_all, const float* __restrict__ lw_all) {
    int idx = blockIdx.x * blockDim.x + threadIdx.x;
    int l = idx / P2_PER, j = idx % P2_PER;
    if (l >= LL) return;
    const float* qw = qw_all + (size_t)l * HD * HD;
    const float* kw = kw_all + (size_t)l * HD * HD;
    const float* vw = vw_all + (size_t)l * HD * HD;
    const float* ew = ew_all + (size_t)l * D64 * HD;
    const float* gw = gw_all + (size_t)l * D64 * D64;
    const float* gb = gb_all + (size_t)l * D64;
    const float* qb = qb_all + (size_t)l * HD;
    const float* kb = kb_all + (size_t)l * HD;
    const float* vb = vb_all + (size_t)l * HD;
    const float* lw = lw_all + (size_t)l * HD * D64;
    const float* qpw = g_qpw[l];
    if (j < 128 * 512) {
        int r = j >> 9, c = j & 511;
        float v;
        if (r < 64) v = wcat_row(qw, kw, vw, qpw, r, c);
        else {
            int d = r - 64;
            float a = 0.f;
            for (int t = 0; t < 64; t++) a += gw[d * 64 + t] * wcat_row(qw, kw, vw, qpw, 64 + t, c);
            v = a;
        }
        g_wcat2[l][j] = v;
    } else if (j < 128 * 512 + 384 * 64) {
        int jj = j - 128 * 512;
        int r = jj >> 6, u = jj & 63;
        float v;
        if (r < 64) v = g_swlw[l][r * 64 + u];
        else if (r < 128) {
            int d = r - 64;
            float a = 0.f;
            for (int t = 0; t < 64; t++) a += gw[d * 64 + t] * g_swlw[l][(64 + t) * 64 + u];
            v = a;
        } else if (r < 256) v = lw[(size_t)(r - 128) * D64 + u];
        else v = g_lw3[l][(r - 256) * 64 + u];
        g_wlin2[l][jj] = v;
    } else if (j < 128 * 512 + 384 * 64 + 512) {
        int c = j - (128 * 512 + 384 * 64);
        float base;
        if (c < 128)      base = qb[c];
        else if (c < 256) base = kb[c - 128];
        else if (c < 384) base = vb[c - 256];
        else {
            int o = c - 384, h = o >> 6, cc = o & 63;
            float a = 0.f;
            for (int d = 0; d < 64; d++) a += qb[h * 64 + d] * ew[cc * HD + h * 64 + d];
            base = a;
        }
        float a = base;
        for (int t = 0; t < 64; t++) a += gb[t] * wcat_row(qw, kw, vw, qpw, 64 + t, c);
        g_bcat2[l][c] = a;
    } else {
        int u = j - (128 * 512 + 384 * 64 + 512);
        float a = g_blb[l][u];
        for (int t = 0; t < 64; t++) a += gb[t] * g_swlw[l][(64 + t) * 64 + u];
        g_blb2[l][u] = a;
    }
}

// ---------------- LN table helper (per-block, FLOAT math from double sums) ----------------
__device__ __forceinline__ void ln_table(const double* __restrict__ ls,
                                         const double* __restrict__ lss,
                                         float* smu, float* srs, int tid) {
    if (tid < GG) {
        float norm = fmaxf(g_cntn[tid] + 1.f, 1.f) * (float)D64;
        float inv = __frcp_rn(norm);
        float mean = (float)ls[tid] * inv;
        float var  = (float)lss[tid] * inv - mean * mean;
        smu[tid] = mean;
        srs[tid] = rsqrtf(var + 1e-5f);
    }
}

// ---------------- gen_conv fused with LN1-apply (merged regular+virtual) ----------------
__global__ void k_gen_all(const float* __restrict__ X,
                          const double* __restrict__ ls, const double* __restrict__ lss) {
    __shared__ float smu[GG], srs[GG];
    __shared__ float sa[64];
    int tid = threadIdx.x;
    ln_table(ls, lss, smu, srs, tid);
    if (blockIdx.x >= NB_GEN && tid < 64) sa[tid] = 0.f;
    __syncthreads();
    if (blockIdx.x < NB_GEN) {
        int i = (blockIdx.x * blockDim.x + tid) >> 5;
        int lane = tid & 31;
        if (i >= NN) return;
        int bi = g_abatch[i];
        float mu_i = smu[bi], rs_i = srs[bi];
        float2 hi = ((const float2*)(X + (size_t)i * D64))[lane];
        hi.x = (hi.x - mu_i) * rs_i;
        hi.y = (hi.y - mu_i) * rs_i;
        ((float2*)(g_big + (size_t)i * 384))[lane] = hi;
        float2 acc = {0.f, 0.f};
        int e0 = g_rowptr[i], e1 = g_rowptr[i + 1];
        for (int e = e0; e < e1; e++) {
            int s = g_esrc[e];
            int bs = g_abatch[s];
            float mu = smu[bs], rs = srs[bs];
            float2 ev = __half22float2(((const __half2*)(g_eperm + (size_t)e * D64))[lane]);
            float2 hv = ((const float2*)(X + (size_t)s * D64))[lane];
            hv.x = (hv.x - mu) * rs;
            hv.y = (hv.y - mu) * rs;
            acc.x += fmaxf(hv.x + ev.x, 0.f) + 1e-7f;
            acc.y += fmaxf(hv.y + ev.y, 0.f) + 1e-7f;
        }
        float2 o = {acc.x + hi.x, acc.y + hi.y};
        ((float2*)(g_big + (size_t)i * 384 + 64))[lane] = o;
    } else {
        int i = NN + (blockIdx.x - NB_GEN);
        int lane = tid & 31, wid = tid >> 5;
        int bi = g_abatch[i];
        float mu_i = smu[bi], rs_i = srs[bi];
        if (wid == 0) {
            float2 hi = ((const float2*)(X + (size_t)i * D64))[lane];
            hi.x = (hi.x - mu_i) * rs_i;
            hi.y = (hi.y - mu_i) * rs_i;
            ((float2*)(g_big + (size_t)i * 384))[lane] = hi;
        }
        int e0 = g_rowptr[i], e1 = g_rowptr[i + 1];
        float2 acc = {0.f, 0.f};
        for (int e = e0 + wid; e < e1; e += 8) {
            int s = g_esrc[e];
            int bs = g_abatch[s];
            float mu = smu[bs], rs = srs[bs];
            float2 ev = __half22float2(((const __half2*)(g_eperm + (size_t)e * D64))[lane]);
            float2 hv = ((const float2*)(X + (size_t)s * D64))[lane];
            hv.x = (hv.x - mu) * rs;
            hv.y = (hv.y - mu) * rs;
            acc.x += fmaxf(hv.x + ev.x, 0.f) + 1e-7f;
            acc.y += fmaxf(hv.y + ev.y, 0.f) + 1e-7f;
        }
        atomicAdd(&sa[2 * lane],     acc.x);
        atomicAdd(&sa[2 * lane + 1], acc.y);
        __syncthreads();
        if (tid < 64) {
            float hn = (X[(size_t)i * D64 + tid] - mu_i) * rs_i;
            g_big[(size_t)i * 384 + 64 + tid] = sa[tid] + hn;
        }
    }
}

// load 4 consecutive fp16 e values starting at element 4*el
__device__ __forceinline__ float4 load_e4(const __half* ep, int el) {
    float2 raw = *(const float2*)(ep + 4 * el);
    float2 a = __half22float2(*(const __half2*)&raw.x);
    float2 b = __half22float2(*(const __half2*)&raw.y);
    return make_float4(a.x, a.y, b.x, b.y);
}

__device__ __forceinline__ float dot8(float4 q4, float4 k4, float4 qp4, float4 e4) {
    return q4.x * k4.x + q4.y * k4.y + q4.z * k4.z + q4.w * k4.w
         + qp4.x * e4.x + qp4.y * e4.y + qp4.z * e4.z + qp4.w * e4.w;
}

__device__ __forceinline__ float bfly4(float p) {
    p += __shfl_xor_sync(0xffffffffu, p, 1);
    p += __shfl_xor_sync(0xffffffffu, p, 2);
    p += __shfl_xor_sync(0xffffffffu, p, 4);
    p += __shfl_xor_sync(0xffffffffu, p, 8);
    return p;
}

__device__ __forceinline__ void attn_upd(float a, float4 v4, float4 e4,
                                         float& mx, float& sum,
                                         float4& vacc, float4& eacc) {
    if (a > mx) {
        float sc = expf(mx - a);
        sum *= sc;
        vacc.x *= sc; vacc.y *= sc; vacc.z *= sc; vacc.w *= sc;
        eacc.x *= sc; eacc.y *= sc; eacc.z *= sc; eacc.w *= sc;
        mx = a;
    }
    float w = expf(a - mx);
    sum += w;
    vacc.x += w * v4.x; vacc.y += w * v4.y; vacc.z += w * v4.z; vacc.w += w * v4.w;
    eacc.x += w * e4.x; eacc.y += w * e4.y; eacc.z += w * e4.z; eacc.w += w * e4.w;
}

// ---------------- fused single-pass attention (merged regular+virtual), 2x unroll ----------------
__global__ void k_attn_all() {
    if (blockIdx.x < NB_GEN) {
        int i = (blockIdx.x * blockDim.x + threadIdx.x) >> 5;
        int lane = threadIdx.x & 31;
        if (i >= NN) return;
        int el = lane & 15;
        float4 q4  = *(const float4*)(g_qkvp + (size_t)i * 512 + 4 * lane);
        float4 qp4 = *(const float4*)(g_qkvp + (size_t)i * 512 + 384 + 4 * lane);
        int e0 = g_rowptr[i], e1 = g_rowptr[i + 1];
        float mx = -INFINITY, sum = 0.f;
        float4 vacc = {0.f, 0.f, 0.f, 0.f};
        float4 eacc = {0.f, 0.f, 0.f, 0.f};
        int e = e0;
        for (; e + 1 < e1; e += 2) {
            int s0 = g_esrc[e], s1 = g_esrc[e + 1];
            float4 k40 = *(const float4*)(g_qkvp + (size_t)s0 * 512 + 128 + 4 * lane);
            float4 k41 = *(const float4*)(g_qkvp + (size_t)s1 * 512 + 128 + 4 * lane);
            float4 e40 = load_e4(g_eperm + (size_t)e * D64, el);
            float4 e41 = load_e4(g_eperm + (size_t)(e + 1) * D64, el);
            float p0 = dot8(q4, k40, qp4, e40);
            float p1 = dot8(q4, k41, qp4, e41);
            p0 = bfly4(p0);
            p1 = bfly4(p1);
            float4 v40 = *(const float4*)(g_qkvp + (size_t)s0 * 512 + 256 + 4 * lane);
            float4 v41 = *(const float4*)(g_qkvp + (size_t)s1 * 512 + 256 + 4 * lane);
            attn_upd(p0 * 0.125f, v40, e40, mx, sum, vacc, eacc);
            attn_upd(p1 * 0.125f, v41, e41, mx, sum, vacc, eacc);
        }
        if (e < e1) {
            int s0 = g_esrc[e];
            float4 k40 = *(const float4*)(g_qkvp + (size_t)s0 * 512 + 128 + 4 * lane);
            float4 e40 = load_e4(g_eperm + (size_t)e * D64, el);
            float p0 = bfly4(dot8(q4, k40, qp4, e40));
            float4 v40 = *(const float4*)(g_qkvp + (size_t)s0 * 512 + 256 + 4 * lane);
            attn_upd(p0 * 0.125f, v40, e40, mx, sum, vacc, eacc);
        }
        float inv = 1.f / (sum + 1e-16f);
        float4 to = {vacc.x * inv, vacc.y * inv, vacc.z * inv, vacc.w * inv};
        float4 wo = {eacc.x * inv, eacc.y * inv, eacc.z * inv, eacc.w * inv};
        *(float4*)(g_big + (size_t)i * 384 + 128 + 4 * lane) = to;
        *(float4*)(g_big + (size_t)i * 384 + 256 + 4 * lane) = wo;
    } else {
        __shared__ float sv[128];
        __shared__ float se[128];
        __shared__ float ssg[2];
        __shared__ float swmx[16];
        __shared__ float gmx[2];
        int i = NN + (blockIdx.x - NB_GEN);
        int tid = threadIdx.x, lane = tid & 31, wid = tid >> 5;
        int el = lane & 15;
        int hh = lane >> 4;
        if (tid < 128) { sv[tid] = 0.f; se[tid] = 0.f; }
        if (tid < 2) ssg[tid] = 0.f;
        __syncthreads();
        float4 q4  = *(const float4*)(g_qkvp + (size_t)i * 512 + 4 * lane);
        float4 qp4 = *(const float4*)(g_qkvp + (size_t)i * 512 + 384 + 4 * lane);
        int e0 = g_rowptr[i], e1 = g_rowptr[i + 1];
        float mx = -INFINITY, sum = 0.f;
        float4 vacc = {0.f, 0.f, 0.f, 0.f};
        float4 eacc = {0.f, 0.f, 0.f, 0.f};
        int e = e0 + wid;
        for (; e + 8 < e1; e += 16) {
            int s0 = g_esrc[e], s1 = g_esrc[e + 8];
            float4 k40 = *(const float4*)(g_qkvp + (size_t)s0 * 512 + 128 + 4 * lane);
            float4 k41 = *(const float4*)(g_qkvp + (size_t)s1 * 512 + 128 + 4 * lane);
            float4 e40 = load_e4(g_eperm + (size_t)e * D64, el);
            float4 e41 = load_e4(g_eperm + (size_t)(e + 8) * D64, el);
            float p0 = dot8(q4, k40, qp4, e40);
            float p1 = dot8(q4, k41, qp4, e41);
            p0 = bfly4(p0);
            p1 = bfly4(p1);
            float4 v40 = *(const float4*)(g_qkvp + (size_t)s0 * 512 + 256 + 4 * lane);
            float4 v41 = *(const float4*)(g_qkvp + (size_t)s1 * 512 + 256 + 4 * lane);
            attn_upd(p0 * 0.125f, v40, e40, mx, sum, vacc, eacc);
            attn_upd(p1 * 0.125f, v41, e41, mx, sum, vacc, eacc);
        }
        if (e < e1) {
            int s0 = g_esrc[e];
            float4 k40 = *(const float4*)(g_qkvp + (size_t)s0 * 512 + 128 + 4 * lane);
            float4 e40 = load_e4(g_eperm + (size_t)e * D64, el);
            float p0 = bfly4(dot8(q4, k40, qp4, e40));
            float4 v40 = *(const float4*)(g_qkvp + (size_t)s0 * 512 + 256 + 4 * lane);
            attn_upd(p0 * 0.125f, v40, e40, mx, sum, vacc, eacc);
        }
        if (el == 0) swmx[wid * 2 + hh] = mx;
        __syncthreads();
        if (tid < 2) {
            float m = -INFINITY;
#pragma unroll
            for (int w = 0; w < 8; w++) m = fmaxf(m, swmx[w * 2 + tid]);
            gmx[tid] = m;
        }
        __syncthreads();
        float sc = expf(mx - gmx[hh]);
        atomicAdd(&sv[4 * lane],     vacc.x * sc); atomicAdd(&sv[4 * lane + 1], vacc.y * sc);
        atomicAdd(&sv[4 * lane + 2], vacc.z * sc); atomicAdd(&sv[4 * lane + 3], vacc.w * sc);
        atomicAdd(&se[4 * lane],     eacc.x * sc); atomicAdd(&se[4 * lane + 1], eacc.y * sc);
        atomicAdd(&se[4 * lane + 2], eacc.z * sc); atomicAdd(&se[4 * lane + 3], eacc.w * sc);
        if (el == 0) atomicAdd(&ssg[hh], sum * sc);
        __syncthreads();
        if (tid < 128) {
            float inv = 1.f / (ssg[tid >> 6] + 1e-16f);
            g_big[(size_t)i * 384 + 128 + tid] = sv[tid] * inv;
            g_big[(size_t)i * 384 + 256 + tid] = se[tid] * inv;
        }
    }
}

// ---------------- bf16 mma helpers ----------------
__device__ __forceinline__ void mma16(float* c, uint32_t a0, uint32_t a1, uint32_t a2,
                                      uint32_t a3, uint32_t b0, uint32_t b1) {
    asm volatile(
        "mma.sync.aligned.m16n8k16.row.col.f32.bf16.bf16.f32 "
        "{%0,%1,%2,%3}, {%4,%5,%6,%7}, {%8,%9}, {%0,%1,%2,%3};"
        : "+f"(c[0]), "+f"(c[1]), "+f"(c[2]), "+f"(c[3])
        : "r"(a0), "r"(a1), "r"(a2), "r"(a3), "r"(b0), "r"(b1));
}

__device__ __forceinline__ void bf_split4(float4 av, __nv_bfloat16* hp, __nv_bfloat16* lp) {
    __nv_bfloat16 h0 = __float2bfloat16_rn(av.x);
    __nv_bfloat16 h1 = __float2bfloat16_rn(av.y);
    __nv_bfloat16 h2 = __float2bfloat16_rn(av.z);
    __nv_bfloat16 h3 = __float2bfloat16_rn(av.w);
    hp[0] = h0; hp[1] = h1; hp[2] = h2; hp[3] = h3;
    lp[0] = __float2bfloat16_rn(av.x - __bfloat162float(h0));
    lp[1] = __float2bfloat16_rn(av.y - __bfloat162float(h1));
    lp[2] = __float2bfloat16_rn(av.z - __bfloat162float(h2));
    lp[3] = __float2bfloat16_rn(av.w - __bfloat162float(h3));
}

// ---------------- A-resident GEMM: 64-row tile, full K in smem, NCB col blocks ----------------
// Static smem: KT=128 -> 46 KB, KT=64 -> 29 KB. Same mma order as streaming (bitwise equal).
template <int KT, int NCB, int ACT, int LNA>
__global__ __launch_bounds__(256) void k_gemm_bfR(
        const float* __restrict__ A, int lda,
        const float* __restrict__ W, int wld,
        const float* __restrict__ bias, float* __restrict__ C,
        int rows, const double* __restrict__ iLs, const double* __restrict__ iLss) {
    constexpr int AP = KT + 8;
    __shared__ __align__(16) __nv_bfloat16 Ah[64][AP];
    __shared__ __align__(16) __nv_bfloat16 Al[64][AP];
    __shared__ __align__(16) __nv_bfloat16 Wh[64][40];
    __shared__ __align__(16) __nv_bfloat16 Wl[64][40];
    __shared__ float smu[GG], srs[GG];
    const int tid = threadIdx.x, lane = tid & 31, warp = tid >> 5;
    const int warpM = warp & 3, warpN = warp >> 2;
    const int gid = lane >> 2, tig = lane & 3;
    const int r0 = blockIdx.x * 64;
    if (LNA) ln_table(iLs, iLss, smu, srs, tid);
    __syncthreads();
    // load full A tile (64 x KT), hi/lo split once
    constexpr int F4 = KT / 4;
#pragma unroll
    for (int t = 0; t < 64 * F4 / 256; t++) {
        int li = tid + t * 256;
        int r = li / F4, kq = li % F4;
        int row = r0 + r;
        float4 av = make_float4(0.f, 0.f, 0.f, 0.f);
        if (row < rows) {
            av = *(const float4*)(A + (size_t)row * lda + kq * 4);
            if (LNA) {
                int b = g_abatch[row];
                float mu = smu[b], rs = srs[b];
                av.x = (av.x - mu) * rs; av.y = (av.y - mu) * rs;
                av.z = (av.z - mu) * rs; av.w = (av.w - mu) * rs;
            }
        }
        bf_split4(av, &Ah[r][kq * 4], &Al[r][kq * 4]);
    }
    __syncthreads();

    for (int cb = 0; cb < NCB; cb++) {
        const int col0 = cb * 64;
        float acc[4][4];
#pragma unroll
        for (int nt = 0; nt < 4; nt++)
#pragma unroll
            for (int r = 0; r < 4; r++) acc[nt][r] = 0.f;
#pragma unroll
        for (int kc = 0; kc < KT / 32; kc++) {
#pragma unroll
            for (int t = 0; t < 2; t++) {
                int li = tid + t * 256;
                int kk = li >> 4, oq = li & 15;
                float4 wv = *(const float4*)(W + (size_t)(kc * 32 + kk) * wld + col0 + oq * 4);
                __nv_bfloat16 hb[4], lb_[4];
                bf_split4(wv, hb, lb_);
#pragma unroll
                for (int jj = 0; jj < 4; jj++) { Wh[oq * 4 + jj][kk] = hb[jj]; Wl[oq * 4 + jj][kk] = lb_[jj]; }
            }
            __syncthreads();
#pragma unroll
            for (int ks = 0; ks < 2; ks++) {
                int kbA = kc * 32 + ks * 16;
                int kbW = ks * 16;
                uint32_t ah[4], al[4];
                int ar = warpM * 16 + gid;
                ah[0] = *(const uint32_t*)&Ah[ar][kbA + 2 * tig];
                ah[1] = *(const uint32_t*)&Ah[ar + 8][kbA + 2 * tig];
                ah[2] = *(const uint32_t*)&Ah[ar][kbA + 2 * tig + 8];
                ah[3] = *(const uint32_t*)&Ah[ar + 8][kbA + 2 * tig + 8];
                al[0] = *(const uint32_t*)&Al[ar][kbA + 2 * tig];
                al[1] = *(const uint32_t*)&Al[ar + 8][kbA + 2 * tig];
                al[2] = *(const uint32_t*)&Al[ar][kbA + 2 * tig + 8];
                al[3] = *(const uint32_t*)&Al[ar + 8][kbA + 2 * tig + 8];
                uint32_t bh[4][2], bl[4][2];
#pragma unroll
                for (int nt = 0; nt < 4; nt++) {
                    int bc = warpN * 32 + nt * 8 + gid;
                    bh[nt][0] = *(const uint32_t*)&Wh[bc][kbW + 2 * tig];
                    bh[nt][1] = *(const uint32_t*)&Wh[bc][kbW + 2 * tig + 8];
                    bl[nt][0] = *(const uint32_t*)&Wl[bc][kbW + 2 * tig];
                    bl[nt][1] = *(const uint32_t*)&Wl[bc][kbW + 2 * tig + 8];
                }
#pragma unroll
                for (int nt = 0; nt < 4; nt++) {
                    mma16(acc[nt], ah[0], ah[1], ah[2], ah[3], bl[nt][0], bl[nt][1]);
                    mma16(acc[nt], al[0], al[1], al[2], al[3], bh[nt][0], bh[nt][1]);
                    mma16(acc[nt], ah[0], ah[1], ah[2], ah[3], bh[nt][0], bh[nt][1]);
                }
            }
            __syncthreads();
        }
        // epilogue for this column block
        int rl = r0 + warpM * 16 + gid;
#pragma unroll
        for (int half = 0; half < 2; half++) {
            int row = rl + half * 8;
            if (row >= rows) continue;
#pragma unroll
            for (int nt = 0; nt < 4; nt++) {
                int col = col0 + warpN * 32 + nt * 8 + tig * 2;
                float v0 = acc[nt][half * 2 + 0] + bias[col];
                float v1 = acc[nt][half * 2 + 1] + bias[col + 1];
                if (ACT == 1) {
                    v0 = (v0 > 0.f) ? v0 : 0.01f * v0;
                    v1 = (v1 > 0.f) ? v1 : 0.01f * v1;
                }
                *(float2*)(C + (size_t)row * (NCB * 64) + col) = make_float2(v0, v1);
            }
        }
    }
}

// ---------------- streaming 3xBF16 GEMM (y=1 only; row-stats epilogue) ----------------
template <int ACT, int ACCUM>
__global__ __launch_bounds__(256) void k_gemm_bf(
        const float* __restrict__ A, int lda,
        const float* __restrict__ W, int wld,
        const float* __restrict__ bias, float* __restrict__ C,
        int rows, int K, double* __restrict__ oLs, double* __restrict__ oLss) {
    __shared__ __align__(16) __nv_bfloat16 Ah[128][40];
    __shared__ __align__(16) __nv_bfloat16 Al[128][40];
    __shared__ __align__(16) __nv_bfloat16 Wh[64][40];
    __shared__ __align__(16) __nv_bfloat16 Wl[64][40];
    __shared__ float sS[128], sSS[128];
    const int tid = threadIdx.x, lane = tid & 31, warp = tid >> 5;
    const int warpM = warp & 3, warpN = warp >> 2;
    const int gid = lane >> 2, tig = lane & 3;
    const int r0 = blockIdx.x * 128;
    if (tid < 128) { sS[tid] = 0.f; sSS[tid] = 0.f; }
    float acc[2][4][4];
#pragma unroll
    for (int mt = 0; mt < 2; mt++)
#pragma unroll
        for (int nt = 0; nt < 4; nt++)
#pragma unroll
            for (int r = 0; r < 4; r++) acc[mt][nt][r] = 0.f;

    for (int k0 = 0; k0 < K; k0 += 32) {
#pragma unroll
        for (int t = 0; t < 4; t++) {
            int li = tid + t * 256;
            int r = li >> 3, kq = li & 7;
            int row = r0 + r;
            float4 av = make_float4(0.f, 0.f, 0.f, 0.f);
            if (row < rows) av = *(const float4*)(A + (size_t)row * lda + k0 + kq * 4);
            bf_split4(av, &Ah[r][kq * 4], &Al[r][kq * 4]);
        }
#pragma unroll
        for (int t = 0; t < 2; t++) {
            int li = tid + t * 256;
            int kk = li >> 4, oq = li & 15;
            float4 wv = *(const float4*)(W + (size_t)(k0 + kk) * wld + oq * 4);
            __nv_bfloat16 hb[4], lb_[4];
            bf_split4(wv, hb, lb_);
#pragma unroll
            for (int jj = 0; jj < 4; jj++) { Wh[oq * 4 + jj][kk] = hb[jj]; Wl[oq * 4 + jj][kk] = lb_[jj]; }
        }
        __syncthreads();
#pragma unroll
        for (int ks = 0; ks < 2; ks++) {
            int kb = ks * 16;
            uint32_t ah[2][4], al[2][4];
#pragma unroll
            for (int mt = 0; mt < 2; mt++) {
                int ar = warpM * 32 + mt * 16 + gid;
                ah[mt][0] = *(const uint32_t*)&Ah[ar][kb + 2 * tig];
                ah[mt][1] = *(const uint32_t*)&Ah[ar + 8][kb + 2 * tig];
                ah[mt][2] = *(const uint32_t*)&Ah[ar][kb + 2 * tig + 8];
                ah[mt][3] = *(const uint32_t*)&Ah[ar + 8][kb + 2 * tig + 8];
                al[mt][0] = *(const uint32_t*)&Al[ar][kb + 2 * tig];
                al[mt][1] = *(const uint32_t*)&Al[ar + 8][kb + 2 * tig];
                al[mt][2] = *(const uint32_t*)&Al[ar][kb + 2 * tig + 8];
                al[mt][3] = *(const uint32_t*)&Al[ar + 8][kb + 2 * tig + 8];
            }
            uint32_t bh[4][2], bl[4][2];
#pragma unroll
            for (int nt = 0; nt < 4; nt++) {
                int bc = warpN * 32 + nt * 8 + gid;
                bh[nt][0] = *(const uint32_t*)&Wh[bc][kb + 2 * tig];
                bh[nt][1] = *(const uint32_t*)&Wh[bc][kb + 2 * tig + 8];
                bl[nt][0] = *(const uint32_t*)&Wl[bc][kb + 2 * tig];
                bl[nt][1] = *(const uint32_t*)&Wl[bc][kb + 2 * tig + 8];
            }
#pragma unroll
            for (int mt = 0; mt < 2; mt++)
#pragma unroll
                for (int nt = 0; nt < 4; nt++) {
                    mma16(acc[mt][nt], ah[mt][0], ah[mt][1], ah[mt][2], ah[mt][3],
                          bl[nt][0], bl[nt][1]);
                    mma16(acc[mt][nt], al[mt][0], al[mt][1], al[mt][2], al[mt][3],
                          bh[nt][0], bh[nt][1]);
                    mma16(acc[mt][nt], ah[mt][0], ah[mt][1], ah[mt][2], ah[mt][3],
                          bh[nt][0], bh[nt][1]);
                }
        }
        __syncthreads();
    }
#pragma unroll
    for (int mt = 0; mt < 2; mt++) {
        int rl = r0 + warpM * 32 + mt * 16 + gid;
#pragma unroll
        for (int half = 0; half < 2; half++) {
            int row = rl + half * 8;
            if (row >= rows) continue;
            float s = 0.f, ss = 0.f;
#pragma unroll
            for (int nt = 0; nt < 4; nt++) {
                int col = warpN * 32 + nt * 8 + tig * 2;
                float v0 = acc[mt][nt][half * 2 + 0];
                float v1 = acc[mt][nt][half * 2 + 1];
                v0 += bias[col]; v1 += bias[col + 1];
                if (ACT == 1) {
                    v0 = (v0 > 0.f) ? v0 : 0.01f * v0;
                    v1 = (v1 > 0.f) ? v1 : 0.01f * v1;
                }
                float2* cp = (float2*)(C + (size_t)row * D64 + col);
                if (ACCUM) { float2 o = *cp; v0 += o.x; v1 += o.y; }
                *cp = make_float2(v0, v1);
                s += v0 + v1; ss += v0 * v0 + v1 * v1;
            }
            int rloc = row - r0;
            atomicAdd(&sS[rloc], s);
            atomicAdd(&sSS[rloc], ss);
        }
    }
    __syncthreads();
    if (tid < 128) {
        int row = r0 + tid;
        if (row < rows) {
            int b = g_abatch[row];
            atomicAdd(&oLs[b], (double)sS[tid]);
            atomicAdd(&oLss[b], (double)sSS[tid]);
        }
    }
}

// ---------------- outputs ----------------
__global__ void k_out1(const int* __restrict__ batch, const int* __restrict__ ne0,
                       const int* __restrict__ ne1, float* __restrict__ out) {
    int idx = blockIdx.x * blockDim.x + threadIdx.x;
    if (idx < NN * D64)
        atomicAdd(&g_gsum[batch[idx >> 6] * D64 + (idx & 63)], g_h[idx]);
    if (idx < NE_ * D64) {
        int j = idx >> 6, d = idx & 63;
        out[(NN + GG) * D64 + idx] = g_h[ne0[j] * D64 + d] + g_h[ne1[j] * D64 + d];
    }
}

__global__ void k_glob_out(float* __restrict__ out) {
    int idx = blockIdx.x * blockDim.x + threadIdx.x;
    if (idx >= GG * D64) return;
    int g = idx >> 6;
    out[NN * D64 + idx] = g_gsum[idx] / fmaxf(g_cntn[g], 1.f) + g_h[NN * D64 + idx];
}

__global__ void k_cleanup() {
    int idx = blockIdx.x * blockDim.x + threadIdx.x;
    if (idx < GG * D64) g_gsum[idx] = 0.f;
    if (idx < NSTAGE * GG) { g_lsum[idx] = 0.0; g_lsumsq[idx] = 0.0; }
    if (idx < GG) g_cntn[idx] = 0.f;
}

// ---------------- host launcher ----------------
#define GETSYM(ptr, sym) do { void* _p; cudaGetSymbolAddress(&_p, sym); ptr = (decltype(ptr))_p; } while (0)

extern "C" void kernel_launch(void* const* d_in, const int* in_sizes, int n_in,
                              void* d_out, int out_size) {
    const float* x          = (const float*)d_in[0];
    const float* cond       = (const float*)d_in[1];
    const float* edge_attr  = (const float*)d_in[2];
    const int*   edge_index = (const int*)d_in[3];
    const int*   ne_index   = (const int*)d_in[4];
    const int*   batch      = (const int*)d_in[5];
    const float* gen_w  = (const float*)d_in[6];
    const float* gen_b  = (const float*)d_in[7];
    const float* q_w    = (const float*)d_in[8];
    const float* q_b    = (const float*)d_in[9];
    const float* k_w    = (const float*)d_in[10];
    const float* k_b    = (const float*)d_in[11];
    const float* v_w    = (const float*)d_in[12];
    const float* v_b    = (const float*)d_in[13];
    const float* e_w    = (const float*)d_in[14];
    const float* skip_w = (const float*)d_in[15];
    const float* skip_b = (const float*)d_in[16];
    const float* lin_w  = (const float*)d_in[17];
    const float* lin_b  = (const float*)d_in[18];
    const float* ff_w1  = (const float*)d_in[19];
    const float* ff_b1  = (const float*)d_in[20];
    const float* ff_w2  = (const float*)d_in[21];
    const float* ff_b2  = (const float*)d_in[22];
    float* out = (float*)d_out;

    float *h_p, *big_p, *qkvp_p, *lh_p, *ffh_p;
    float *wcat2_p, *bcat2_p, *wlin2_p, *blb2_p;
    double *ls_p, *lss_p;
    GETSYM(h_p, g_h);       GETSYM(big_p, g_big);   GETSYM(qkvp_p, g_qkvp);
    GETSYM(lh_p, g_lh);     GETSYM(ffh_p, g_ffh);
    GETSYM(wcat2_p, g_wcat2); GETSYM(bcat2_p, g_bcat2);
    GETSYM(wlin2_p, g_wlin2); GETSYM(blb2_p, g_blb2);
    GETSYM(ls_p, g_lsum);   GETSYM(lss_p, g_lsumsq);

    const int T = 256;
    const int GRID_N  = CDIV(NAUG, 128);
    const int GRID_N64 = CDIV(NAUG, 64);
    cudaStream_t st = 0;

    // ---- setup (9 launches) ----
    k_build_edges<<<CDIV(MM, T), T, 0, st>>>(edge_index, edge_index + EE, batch);
    k_scanA<<<NB_SCAN, 256, 0, st>>>();
    k_scanB<<<1, 256, 0, st>>>();
    k_scanC<<<NB_SCAN, 256, 0, st>>>();
    k_scatter<<<CDIV(MM, T), T, 0, st>>>();
    k_misc<<<CDIV(NAUG * D64, T), T, 0, st>>>(x, cond, batch);
    k_eperm<<<CDIV(NAUG * 32, T), T, 0, st>>>(edge_attr);
    k_prep1<<<CDIV(LL * P1_PER, T), T, 0, st>>>(q_w, e_w, skip_w, lin_w, skip_b, lin_b);
    k_prep2<<<CDIV(LL * P2_PER, T), T, 0, st>>>(q_w, k_w, v_w, e_w, gen_w, gen_b,
                                                q_b, k_b, v_b, lin_w);

    // ---- layers (6 launches each) ----
    for (int i = 0; i < LL; i++) {
        const float* f1w = ff_w1 + (size_t)i * D64 * 4 * D64;
        const float* f1b = ff_b1 + (size_t)i * 4 * D64;
        const float* f2w = ff_w2 + (size_t)i * 4 * D64 * D64;
        const float* f2b = ff_b2 + (size_t)i * D64;
        float* wc2 = wcat2_p + (size_t)i * HD * 512;
        float* bc2 = bcat2_p + (size_t)i * 512;
        float* wl2 = wlin2_p + (size_t)i * 384 * D64;
        float* bl2 = blb2_p  + (size_t)i * D64;
        double* stLN1  = ls_p  + (size_t)(2 * i) * GG;
        double* stLN1s = lss_p + (size_t)(2 * i) * GG;
        double* stLN2  = ls_p  + (size_t)(2 * i + 1) * GG;
        double* stLN2s = lss_p + (size_t)(2 * i + 1) * GG;
        double* stNx   = ls_p  + (size_t)(2 * i + 2) * GG;
        double* stNxs  = lss_p + (size_t)(2 * i + 2) * GG;

        k_gen_all<<<NB_GEN + GG, T, 0, st>>>(h_p, stLN1, stLN1s);
        // qkvp = big[:,0:128] @ wcat2 + bcat2  (A-resident, 8 col blocks)
        k_gemm_bfR<128, 8, 0, 0><<<GRID_N64, T, 0, st>>>(
            big_p, 384, wc2, 512, bc2, qkvp_p, NAUG, nullptr, nullptr);
        k_attn_all<<<NB_GEN + GG, T, 0, st>>>();
        // lh = big @ wlin2 + blb2 (+ LN2 stats)
        k_gemm_bf<0, 0><<<GRID_N, T, 0, st>>>(
            big_p, 384, wl2, D64, bl2, lh_p, NAUG, 384, stLN2, stLN2s);
        // ffh = leaky(LN2(lh) @ f1w + f1b)  (A-resident, 4 col blocks, LN inline)
        k_gemm_bfR<64, 4, 1, 1><<<GRID_N64, T, 0, st>>>(
            lh_p, D64, f1w, 256, f1b, ffh_p, NAUG, stLN2, stLN2s);
        // h += ffh @ f2w + f2b (+ next-layer LN1 stats)
        k_gemm_bf<0, 1><<<GRID_N, T, 0, st>>>(
            ffh_p, 256, f2w, D64, f2b, h_p, NAUG, 256, stNx, stNxs);
    }

    // ---- outputs ----
    cudaMemcpyAsync(out, h_p, sizeof(float) * NN * D64, cudaMemcpyDeviceToDevice, st);
    k_out1<<<CDIV(NE_ * D64, T), T, 0, st>>>(batch, ne_index, ne_index + NE_, out);
    k_glob_out<<<CDIV(GG * D64, T), T, 0, st>>>(out);
    k_cleanup<<<CDIV(NSTAGE * GG, T) > CDIV(GG * D64, T) ? CDIV(NSTAGE * GG, T)
                                                         : CDIV(GG * D64, T), T, 0, st>>>();
}

// round 17
// speedup vs baseline: 1.1172x; 1.1172x over previous
#include <cuda_runtime.h>
#include <cuda_bf16.h>
#include <cuda_fp16.h>
#include <math.h>
#include <stdint.h>

// Problem constants
#define D64   64
#define HH    2
#define HD    128
#define LL    3
#define NN    50000
#define GG    128
#define EE    600000
#define NE_   300000
#define NAUG  (NN + GG)          // 50128
#define M0    (EE + 2 * NN)      // 700000
#define MM    (M0 + NAUG)        // 750128
#define NB_SCAN ((NAUG + 255) / 256)   // 196
#define NB_GEN  ((NN * 32 + 255) / 256)
#define NSTAGE (2 * LL + 1)      // 7 LN-stats stages

#define CDIV(a, b) (((a) + (b) - 1) / (b))

// ---------------- device scratch (static, no allocs) ----------------
__device__ int    g_src[MM];
__device__ int    g_dst[MM];
__device__ int    g_deg[NAUG];
__device__ int    g_rowptr[NAUG + 1];
__device__ int    g_bsum[256];
__device__ int    g_fill[NAUG];
__device__ int    g_esrc[MM];
__device__ int    g_eid[MM];
__device__ __half g_eperm[(size_t)MM * D64];     // e_aug rows in CSR order, fp16
__device__ float  g_h[NAUG * D64];
__device__ float  g_big[(size_t)NAUG * 384];     // [hn|geno | t | we]
__device__ float  g_qkvp[(size_t)NAUG * 512];    // [q | k | v | qp]
__device__ float  g_lh[NAUG * D64];
__device__ float  g_ffh[(size_t)NAUG * 256];
// per-layer precomputed weights
__device__ float  g_qpw[LL][HD * HD];
__device__ float  g_swlw[LL][HD * D64];
__device__ float  g_lw3[LL][HD * D64];
__device__ float  g_blb[LL][D64];
__device__ float  g_wcat2[LL][HD * 512];
__device__ float  g_bcat2[LL][512];
__device__ float  g_wlin2[LL][384 * D64];
__device__ float  g_blb2[LL][D64];
// LN stage buffers / misc
__device__ float  g_cntn[GG];
__device__ double g_lsum[NSTAGE * GG];
__device__ double g_lsumsq[NSTAGE * GG];
__device__ int    g_abatch[NAUG];
__device__ float  g_gsum[GG * D64];

// ---------------- setup kernels ----------------
__global__ void k_build_edges(const int* __restrict__ ei0, const int* __restrict__ ei1,
                              const int* __restrict__ batch) {
    int m = blockIdx.x * blockDim.x + threadIdx.x;
    if (m >= MM) return;
    int s, d;
    if (m < EE)               { s = ei0[m]; d = ei1[m]; }
    else if (m < EE + NN)     { int i = m - EE;          s = i;             d = batch[i] + NN; }
    else if (m < EE + 2 * NN) { int i = m - EE - NN;     s = batch[i] + NN; d = i; }
    else                      { int i = m - EE - 2 * NN; s = i;             d = i; }
    g_src[m] = s; g_dst[m] = d;
    atomicAdd(&g_deg[d], 1);
}

__global__ void k_scanA() {
    __shared__ int sh[256];
    int t = threadIdx.x;
    int i = blockIdx.x * 256 + t;
    int v = (i < NAUG) ? g_deg[i] : 0;
    sh[t] = v;
    __syncthreads();
    for (int off = 1; off < 256; off <<= 1) {
        int a = (t >= off) ? sh[t - off] : 0;
        __syncthreads();
        sh[t] += a;
        __syncthreads();
    }
    if (i < NAUG) g_rowptr[i] = sh[t] - v;
    if (t == 255) g_bsum[blockIdx.x] = sh[255];
}

__global__ void k_scanB() {
    __shared__ int sh[256];
    int t = threadIdx.x;
    int v = (t < NB_SCAN) ? g_bsum[t] : 0;
    sh[t] = v;
    __syncthreads();
    for (int off = 1; off < 256; off <<= 1) {
        int a = (t >= off) ? sh[t - off] : 0;
        __syncthreads();
        sh[t] += a;
        __syncthreads();
    }
    if (t < NB_SCAN) g_bsum[t] = sh[t] - v;
}

__global__ void k_scanC() {
    int i = blockIdx.x * 256 + threadIdx.x;
    if (i < NAUG) {
        int r = g_rowptr[i] + g_bsum[i >> 8];
        g_rowptr[i] = r;
        g_fill[i] = r;
        g_deg[i] = 0;
    }
    if (i == 0) g_rowptr[NAUG] = MM;
}

__global__ void k_scatter() {
    int m = blockIdx.x * blockDim.x + threadIdx.x;
    if (m >= MM) return;
    int pos = atomicAdd(&g_fill[g_dst[m]], 1);
    g_esrc[pos] = g_src[m];
    g_eid[pos]  = m;
}

// fused misc setup: init h, abatch, cntn, layer-0 LN1 stats (stage 0)
__global__ void k_misc(const float* __restrict__ x, const float* __restrict__ cond,
                       const int* __restrict__ batch) {
    int idx = blockIdx.x * blockDim.x + threadIdx.x;
    if (idx < NAUG * D64)
        g_h[idx] = (idx < NN * D64) ? x[idx] : cond[idx - NN * D64];
    if (idx < NAUG)
        g_abatch[idx] = (idx < NN) ? batch[idx] : (idx - NN);
    if (idx < NN)
        atomicAdd(&g_cntn[batch[idx]], 1.f);
    int w = idx >> 5, lane = idx & 31;
    if (w < NAUG) {
        const float* src = (w < NN) ? x + (size_t)w * D64 : cond + (size_t)(w - NN) * D64;
        float2 v = ((const float2*)src)[lane];
        float s = v.x + v.y, ss = v.x * v.x + v.y * v.y;
#pragma unroll
        for (int off = 16; off; off >>= 1) {
            s  += __shfl_xor_sync(0xffffffffu, s, off);
            ss += __shfl_xor_sync(0xffffffffu, ss, off);
        }
        if (lane == 0) {
            int b = (w < NN) ? batch[w] : (w - NN);
            atomicAdd(&g_lsum[b], (double)s);
            atomicAdd(&g_lsumsq[b], (double)ss);
        }
    }
}

// fused eperm build: warp per node; fp16 rows in CSR order, self-loop filled last.
__global__ void k_eperm(const float* __restrict__ edge_attr) {
    int i = (blockIdx.x * blockDim.x + threadIdx.x) >> 5;
    int lane = threadIdx.x & 31;
    if (i >= NAUG) return;
    float2 acc = {0.f, 0.f};
    float cnt = 0.f;
    int loopPos = -1;
    int e0 = g_rowptr[i], e1 = g_rowptr[i + 1];
    for (int e = e0; e < e1; e++) {
        int m = g_eid[e];
        float2 ev;
        if (m < EE) {
            ev = ((const float2*)(edge_attr + (size_t)m * D64))[lane];
            acc.x += ev.x; acc.y += ev.y;
            cnt += 1.f;
        } else if (m < M0) {
            ev = make_float2((lane == 0) ? 1.f : 0.f, 0.f);
            acc.x += ev.x;
            cnt += 1.f;
        } else {
            loopPos = e;
            continue;
        }
        ((__half2*)(g_eperm + (size_t)e * D64))[lane] = __floats2half2_rn(ev.x, ev.y);
    }
    float invc = 1.f / fmaxf(cnt, 1.f);
    if (loopPos >= 0)
        ((__half2*)(g_eperm + (size_t)loopPos * D64))[lane] =
            __floats2half2_rn(acc.x * invc, acc.y * invc);
}

// ---------------- batched weight prep ----------------
#define P1_PER (128 * 128 + 128 * 64 + 128 * 64 + 64)
__global__ void k_prep1(const float* __restrict__ qw_all, const float* __restrict__ ew_all,
                        const float* __restrict__ sw_all, const float* __restrict__ lw_all,
                        const float* __restrict__ sb_all, const float* __restrict__ lb_all) {
    int idx = blockIdx.x * blockDim.x + threadIdx.x;
    int l = idx / P1_PER, j = idx % P1_PER;
    if (l >= LL) return;
    const float* qw = qw_all + (size_t)l * HD * HD;
    const float* ew = ew_all + (size_t)l * D64 * HD;
    const float* sw = sw_all + (size_t)l * HD * HD;
    const float* lw = lw_all + (size_t)l * HD * D64;
    const float* sb = sb_all + (size_t)l * HD;
    const float* lb = lb_all + (size_t)l * D64;
    if (j < 128 * 128) {
        int xx = j >> 7, o = j & 127;
        int h = o >> 6, c = o & 63;
        float a = 0.f;
        for (int d = 0; d < 64; d++) a += qw[xx * HD + h * 64 + d] * ew[c * HD + h * 64 + d];
        g_qpw[l][j] = a;
    } else if (j < 128 * 128 + 128 * 64) {
        int jj = j - 128 * 128;
        int r = jj >> 6, u = jj & 63;
        float a = 0.f;
        for (int k2 = 0; k2 < 128; k2++) a += sw[r * HD + k2] * lw[k2 * D64 + u];
        g_swlw[l][jj] = a;
    } else if (j < 128 * 128 + 2 * 128 * 64) {
        int jj = j - 128 * 128 - 128 * 64;
        int r = jj >> 6, u = jj & 63;
        int h = r >> 6, c = r & 63;
        float a = 0.f;
        for (int o2 = 0; o2 < 64; o2++)
            a += ew[c * HD + h * 64 + o2] * lw[(h * 64 + o2) * D64 + u];
        g_lw3[l][jj] = a;
    } else {
        int o = j - 128 * 128 - 2 * 128 * 64;
        float a = lb[o];
        for (int k2 = 0; k2 < 128; k2++) a += sb[k2] * lw[k2 * D64 + o];
        g_blb[l][o] = a;
    }
}

__device__ __forceinline__ float wcat_row(const float* qw, const float* kw,
                                          const float* vw, const float* qpw,
                                          int r, int c) {
    if (c < 128) return qw[r * HD + c];
    if (c < 256) return kw[r * HD + c - 128];
    if (c < 384) return vw[r * HD + c - 256];
    return qpw[r * HD + c - 384];
}

#define P2_PER (128 * 512 + 384 * 64 + 512 + 64)
__global__ void k_prep2(const float* __restrict__ qw_all, const float* __restrict__ kw_all,
                        const float* __restrict__ vw_all, const float* __restrict__ ew_all,
                        const float* __restrict__ gw_all, const float* __restrict__ gb_all,
                        const float* __restrict__ qb_all, const float* __restrict__ kb_all,
                        const float* __restrict__ vb_all, const float* __restrict__ lw_all) {
    int idx = blockIdx.x * blockDim.x + threadIdx.x;
    int l = idx / P2_PER, j = idx % P2_PER;
    if (l >= LL) return;
    const float* qw = qw_all + (size_t)l * HD * HD;
    const float* kw = kw_all + (size_t)l * HD * HD;
    const float* vw = vw_all + (size_t)l * HD * HD;
    const float* ew = ew_all + (size_t)l * D64 * HD;
    const float* gw = gw_all + (size_t)l * D64 * D64;
    const float* gb = gb_all + (size_t)l * D64;
    const float* qb = qb_all + (size_t)l * HD;
    const float* kb = kb_all + (size_t)l * HD;
    const float* vb = vb_all + (size_t)l * HD;
    const float* lw = lw_all + (size_t)l * HD * D64;
    const float* qpw = g_qpw[l];
    if (j < 128 * 512) {
        int r = j >> 9, c = j & 511;
        float v;
        if (r < 64) v = wcat_row(qw, kw, vw, qpw, r, c);
        else {
            int d = r - 64;
            float a = 0.f;
            for (int t = 0; t < 64; t++) a += gw[d * 64 + t] * wcat_row(qw, kw, vw, qpw, 64 + t, c);
            v = a;
        }
        g_wcat2[l][j] = v;
    } else if (j < 128 * 512 + 384 * 64) {
        int jj = j - 128 * 512;
        int r = jj >> 6, u = jj & 63;
        float v;
        if (r < 64) v = g_swlw[l][r * 64 + u];
        else if (r < 128) {
            int d = r - 64;
            float a = 0.f;
            for (int t = 0; t < 64; t++) a += gw[d * 64 + t] * g_swlw[l][(64 + t) * 64 + u];
            v = a;
        } else if (r < 256) v = lw[(size_t)(r - 128) * D64 + u];
        else v = g_lw3[l][(r - 256) * 64 + u];
        g_wlin2[l][jj] = v;
    } else if (j < 128 * 512 + 384 * 64 + 512) {
        int c = j - (128 * 512 + 384 * 64);
        float base;
        if (c < 128)      base = qb[c];
        else if (c < 256) base = kb[c - 128];
        else if (c < 384) base = vb[c - 256];
        else {
            int o = c - 384, h = o >> 6, cc = o & 63;
            float a = 0.f;
            for (int d = 0; d < 64; d++) a += qb[h * 64 + d] * ew[cc * HD + h * 64 + d];
            base = a;
        }
        float a = base;
        for (int t = 0; t < 64; t++) a += gb[t] * wcat_row(qw, kw, vw, qpw, 64 + t, c);
        g_bcat2[l][c] = a;
    } else {
        int u = j - (128 * 512 + 384 * 64 + 512);
        float a = g_blb[l][u];
        for (int t = 0; t < 64; t++) a += gb[t] * g_swlw[l][(64 + t) * 64 + u];
        g_blb2[l][u] = a;
    }
}

// ---------------- LN table helper (per-block, FLOAT math from double sums) ----------------
__device__ __forceinline__ void ln_table(const double* __restrict__ ls,
                                         const double* __restrict__ lss,
                                         float* smu, float* srs, int tid) {
    if (tid < GG) {
        float norm = fmaxf(g_cntn[tid] + 1.f, 1.f) * (float)D64;
        float inv = __frcp_rn(norm);
        float mean = (float)ls[tid] * inv;
        float var  = (float)lss[tid] * inv - mean * mean;
        smu[tid] = mean;
        srs[tid] = rsqrtf(var + 1e-5f);
    }
}

// ---------------- gen_conv fused with LN1-apply (merged regular+virtual) ----------------
__global__ void k_gen_all(const float* __restrict__ X,
                          const double* __restrict__ ls, const double* __restrict__ lss) {
    __shared__ float smu[GG], srs[GG];
    __shared__ float sa[64];
    int tid = threadIdx.x;
    ln_table(ls, lss, smu, srs, tid);
    if (blockIdx.x >= NB_GEN && tid < 64) sa[tid] = 0.f;
    __syncthreads();
    if (blockIdx.x < NB_GEN) {
        int i = (blockIdx.x * blockDim.x + tid) >> 5;
        int lane = tid & 31;
        if (i >= NN) return;
        int bi = g_abatch[i];
        float mu_i = smu[bi], rs_i = srs[bi];
        float2 hi = ((const float2*)(X + (size_t)i * D64))[lane];
        hi.x = (hi.x - mu_i) * rs_i;
        hi.y = (hi.y - mu_i) * rs_i;
        ((float2*)(g_big + (size_t)i * 384))[lane] = hi;
        float2 acc = {0.f, 0.f};
        int e0 = g_rowptr[i], e1 = g_rowptr[i + 1];
        for (int e = e0; e < e1; e++) {
            int s = g_esrc[e];
            int bs = g_abatch[s];
            float mu = smu[bs], rs = srs[bs];
            float2 ev = __half22float2(((const __half2*)(g_eperm + (size_t)e * D64))[lane]);
            float2 hv = ((const float2*)(X + (size_t)s * D64))[lane];
            hv.x = (hv.x - mu) * rs;
            hv.y = (hv.y - mu) * rs;
            acc.x += fmaxf(hv.x + ev.x, 0.f) + 1e-7f;
            acc.y += fmaxf(hv.y + ev.y, 0.f) + 1e-7f;
        }
        float2 o = {acc.x + hi.x, acc.y + hi.y};
        ((float2*)(g_big + (size_t)i * 384 + 64))[lane] = o;
    } else {
        int i = NN + (blockIdx.x - NB_GEN);
        int lane = tid & 31, wid = tid >> 5;
        int bi = g_abatch[i];
        float mu_i = smu[bi], rs_i = srs[bi];
        if (wid == 0) {
            float2 hi = ((const float2*)(X + (size_t)i * D64))[lane];
            hi.x = (hi.x - mu_i) * rs_i;
            hi.y = (hi.y - mu_i) * rs_i;
            ((float2*)(g_big + (size_t)i * 384))[lane] = hi;
        }
        int e0 = g_rowptr[i], e1 = g_rowptr[i + 1];
        float2 acc = {0.f, 0.f};
        for (int e = e0 + wid; e < e1; e += 8) {
            int s = g_esrc[e];
            int bs = g_abatch[s];
            float mu = smu[bs], rs = srs[bs];
            float2 ev = __half22float2(((const __half2*)(g_eperm + (size_t)e * D64))[lane]);
            float2 hv = ((const float2*)(X + (size_t)s * D64))[lane];
            hv.x = (hv.x - mu) * rs;
            hv.y = (hv.y - mu) * rs;
            acc.x += fmaxf(hv.x + ev.x, 0.f) + 1e-7f;
            acc.y += fmaxf(hv.y + ev.y, 0.f) + 1e-7f;
        }
        atomicAdd(&sa[2 * lane],     acc.x);
        atomicAdd(&sa[2 * lane + 1], acc.y);
        __syncthreads();
        if (tid < 64) {
            float hn = (X[(size_t)i * D64 + tid] - mu_i) * rs_i;
            g_big[(size_t)i * 384 + 64 + tid] = sa[tid] + hn;
        }
    }
}

// load 4 consecutive fp16 e values starting at element 4*el
__device__ __forceinline__ float4 load_e4(const __half* ep, int el) {
    float2 raw = *(const float2*)(ep + 4 * el);
    float2 a = __half22float2(*(const __half2*)&raw.x);
    float2 b = __half22float2(*(const __half2*)&raw.y);
    return make_float4(a.x, a.y, b.x, b.y);
}

__device__ __forceinline__ float dot8(float4 q4, float4 k4, float4 qp4, float4 e4) {
    return q4.x * k4.x + q4.y * k4.y + q4.z * k4.z + q4.w * k4.w
         + qp4.x * e4.x + qp4.y * e4.y + qp4.z * e4.z + qp4.w * e4.w;
}

__device__ __forceinline__ float bfly4(float p) {
    p += __shfl_xor_sync(0xffffffffu, p, 1);
    p += __shfl_xor_sync(0xffffffffu, p, 2);
    p += __shfl_xor_sync(0xffffffffu, p, 4);
    p += __shfl_xor_sync(0xffffffffu, p, 8);
    return p;
}

__device__ __forceinline__ void attn_upd(float a, float4 v4, float4 e4,
                                         float& mx, float& sum,
                                         float4& vacc, float4& eacc) {
    if (a > mx) {
        float sc = expf(mx - a);
        sum *= sc;
        vacc.x *= sc; vacc.y *= sc; vacc.z *= sc; vacc.w *= sc;
        eacc.x *= sc; eacc.y *= sc; eacc.z *= sc; eacc.w *= sc;
        mx = a;
    }
    float w = expf(a - mx);
    sum += w;
    vacc.x += w * v4.x; vacc.y += w * v4.y; vacc.z += w * v4.z; vacc.w += w * v4.w;
    eacc.x += w * e4.x; eacc.y += w * e4.y; eacc.z += w * e4.z; eacc.w += w * e4.w;
}

// ---------------- fused single-pass attention (merged regular+virtual), 2x unroll ----------------
__global__ void k_attn_all() {
    if (blockIdx.x < NB_GEN) {
        int i = (blockIdx.x * blockDim.x + threadIdx.x) >> 5;
        int lane = threadIdx.x & 31;
        if (i >= NN) return;
        int el = lane & 15;
        float4 q4  = *(const float4*)(g_qkvp + (size_t)i * 512 + 4 * lane);
        float4 qp4 = *(const float4*)(g_qkvp + (size_t)i * 512 + 384 + 4 * lane);
        int e0 = g_rowptr[i], e1 = g_rowptr[i + 1];
        float mx = -INFINITY, sum = 0.f;
        float4 vacc = {0.f, 0.f, 0.f, 0.f};
        float4 eacc = {0.f, 0.f, 0.f, 0.f};
        int e = e0;
        for (; e + 1 < e1; e += 2) {
            int s0 = g_esrc[e], s1 = g_esrc[e + 1];
            float4 k40 = *(const float4*)(g_qkvp + (size_t)s0 * 512 + 128 + 4 * lane);
            float4 k41 = *(const float4*)(g_qkvp + (size_t)s1 * 512 + 128 + 4 * lane);
            float4 e40 = load_e4(g_eperm + (size_t)e * D64, el);
            float4 e41 = load_e4(g_eperm + (size_t)(e + 1) * D64, el);
            float p0 = dot8(q4, k40, qp4, e40);
            float p1 = dot8(q4, k41, qp4, e41);
            p0 = bfly4(p0);
            p1 = bfly4(p1);
            float4 v40 = *(const float4*)(g_qkvp + (size_t)s0 * 512 + 256 + 4 * lane);
            float4 v41 = *(const float4*)(g_qkvp + (size_t)s1 * 512 + 256 + 4 * lane);
            attn_upd(p0 * 0.125f, v40, e40, mx, sum, vacc, eacc);
            attn_upd(p1 * 0.125f, v41, e41, mx, sum, vacc, eacc);
        }
        if (e < e1) {
            int s0 = g_esrc[e];
            float4 k40 = *(const float4*)(g_qkvp + (size_t)s0 * 512 + 128 + 4 * lane);
            float4 e40 = load_e4(g_eperm + (size_t)e * D64, el);
            float p0 = bfly4(dot8(q4, k40, qp4, e40));
            float4 v40 = *(const float4*)(g_qkvp + (size_t)s0 * 512 + 256 + 4 * lane);
            attn_upd(p0 * 0.125f, v40, e40, mx, sum, vacc, eacc);
        }
        float inv = 1.f / (sum + 1e-16f);
        float4 to = {vacc.x * inv, vacc.y * inv, vacc.z * inv, vacc.w * inv};
        float4 wo = {eacc.x * inv, eacc.y * inv, eacc.z * inv, eacc.w * inv};
        *(float4*)(g_big + (size_t)i * 384 + 128 + 4 * lane) = to;
        *(float4*)(g_big + (size_t)i * 384 + 256 + 4 * lane) = wo;
    } else {
        __shared__ float sv[128];
        __shared__ float se[128];
        __shared__ float ssg[2];
        __shared__ float swmx[16];
        __shared__ float gmx[2];
        int i = NN + (blockIdx.x - NB_GEN);
        int tid = threadIdx.x, lane = tid & 31, wid = tid >> 5;
        int el = lane & 15;
        int hh = lane >> 4;
        if (tid < 128) { sv[tid] = 0.f; se[tid] = 0.f; }
        if (tid < 2) ssg[tid] = 0.f;
        __syncthreads();
        float4 q4  = *(const float4*)(g_qkvp + (size_t)i * 512 + 4 * lane);
        float4 qp4 = *(const float4*)(g_qkvp + (size_t)i * 512 + 384 + 4 * lane);
        int e0 = g_rowptr[i], e1 = g_rowptr[i + 1];
        float mx = -INFINITY, sum = 0.f;
        float4 vacc = {0.f, 0.f, 0.f, 0.f};
        float4 eacc = {0.f, 0.f, 0.f, 0.f};
        int e = e0 + wid;
        for (; e + 8 < e1; e += 16) {
            int s0 = g_esrc[e], s1 = g_esrc[e + 8];
            float4 k40 = *(const float4*)(g_qkvp + (size_t)s0 * 512 + 128 + 4 * lane);
            float4 k41 = *(const float4*)(g_qkvp + (size_t)s1 * 512 + 128 + 4 * lane);
            float4 e40 = load_e4(g_eperm + (size_t)e * D64, el);
            float4 e41 = load_e4(g_eperm + (size_t)(e + 8) * D64, el);
            float p0 = dot8(q4, k40, qp4, e40);
            float p1 = dot8(q4, k41, qp4, e41);
            p0 = bfly4(p0);
            p1 = bfly4(p1);
            float4 v40 = *(const float4*)(g_qkvp + (size_t)s0 * 512 + 256 + 4 * lane);
            float4 v41 = *(const float4*)(g_qkvp + (size_t)s1 * 512 + 256 + 4 * lane);
            attn_upd(p0 * 0.125f, v40, e40, mx, sum, vacc, eacc);
            attn_upd(p1 * 0.125f, v41, e41, mx, sum, vacc, eacc);
        }
        if (e < e1) {
            int s0 = g_esrc[e];
            float4 k40 = *(const float4*)(g_qkvp + (size_t)s0 * 512 + 128 + 4 * lane);
            float4 e40 = load_e4(g_eperm + (size_t)e * D64, el);
            float p0 = bfly4(dot8(q4, k40, qp4, e40));
            float4 v40 = *(const float4*)(g_qkvp + (size_t)s0 * 512 + 256 + 4 * lane);
            attn_upd(p0 * 0.125f, v40, e40, mx, sum, vacc, eacc);
        }
        if (el == 0) swmx[wid * 2 + hh] = mx;
        __syncthreads();
        if (tid < 2) {
            float m = -INFINITY;
#pragma unroll
            for (int w = 0; w < 8; w++) m = fmaxf(m, swmx[w * 2 + tid]);
            gmx[tid] = m;
        }
        __syncthreads();
        float sc = expf(mx - gmx[hh]);
        atomicAdd(&sv[4 * lane],     vacc.x * sc); atomicAdd(&sv[4 * lane + 1], vacc.y * sc);
        atomicAdd(&sv[4 * lane + 2], vacc.z * sc); atomicAdd(&sv[4 * lane + 3], vacc.w * sc);
        atomicAdd(&se[4 * lane],     eacc.x * sc); atomicAdd(&se[4 * lane + 1], eacc.y * sc);
        atomicAdd(&se[4 * lane + 2], eacc.z * sc); atomicAdd(&se[4 * lane + 3], eacc.w * sc);
        if (el == 0) atomicAdd(&ssg[hh], sum * sc);
        __syncthreads();
        if (tid < 128) {
            float inv = 1.f / (ssg[tid >> 6] + 1e-16f);
            g_big[(size_t)i * 384 + 128 + tid] = sv[tid] * inv;
            g_big[(size_t)i * 384 + 256 + tid] = se[tid] * inv;
        }
    }
}

// ---------------- bf16 mma helpers ----------------
__device__ __forceinline__ void mma16(float* c, uint32_t a0, uint32_t a1, uint32_t a2,
                                      uint32_t a3, uint32_t b0, uint32_t b1) {
    asm volatile(
        "mma.sync.aligned.m16n8k16.row.col.f32.bf16.bf16.f32 "
        "{%0,%1,%2,%3}, {%4,%5,%6,%7}, {%8,%9}, {%0,%1,%2,%3};"
        : "+f"(c[0]), "+f"(c[1]), "+f"(c[2]), "+f"(c[3])
        : "r"(a0), "r"(a1), "r"(a2), "r"(a3), "r"(b0), "r"(b1));
}

__device__ __forceinline__ void bf_split4(float4 av, __nv_bfloat16* hp, __nv_bfloat16* lp) {
    __nv_bfloat16 h0 = __float2bfloat16_rn(av.x);
    __nv_bfloat16 h1 = __float2bfloat16_rn(av.y);
    __nv_bfloat16 h2 = __float2bfloat16_rn(av.z);
    __nv_bfloat16 h3 = __float2bfloat16_rn(av.w);
    hp[0] = h0; hp[1] = h1; hp[2] = h2; hp[3] = h3;
    lp[0] = __float2bfloat16_rn(av.x - __bfloat162float(h0));
    lp[1] = __float2bfloat16_rn(av.y - __bfloat162float(h1));
    lp[2] = __float2bfloat16_rn(av.z - __bfloat162float(h2));
    lp[3] = __float2bfloat16_rn(av.w - __bfloat162float(h3));
}

// ---------------- streaming 3xBF16 GEMM (inline float LN table) ----------------
// STATS=1 requires gridDim.y == 1 and ldc == 64.
template <int ACT, int ACCUM, int LNA, int STATS>
__global__ __launch_bounds__(256) void k_gemm_bf(
        const float* __restrict__ A, int lda,
        const float* __restrict__ W, int wld,
        const float* __restrict__ bias, float* __restrict__ C,
        int ldc, int rows, int K,
        const double* __restrict__ iLs, const double* __restrict__ iLss,
        double* __restrict__ oLs, double* __restrict__ oLss) {
    __shared__ __align__(16) __nv_bfloat16 Ah[128][40];
    __shared__ __align__(16) __nv_bfloat16 Al[128][40];
    __shared__ __align__(16) __nv_bfloat16 Wh[64][40];
    __shared__ __align__(16) __nv_bfloat16 Wl[64][40];
    __shared__ float sS[128], sSS[128];
    __shared__ float smu[GG], srs[GG];
    const int tid = threadIdx.x, lane = tid & 31, warp = tid >> 5;
    const int warpM = warp & 3, warpN = warp >> 2;
    const int gid = lane >> 2, tig = lane & 3;
    const int r0 = blockIdx.x * 128, col0 = blockIdx.y * 64;
    if (STATS && tid < 128) { sS[tid] = 0.f; sSS[tid] = 0.f; }
    if (LNA) {
        ln_table(iLs, iLss, smu, srs, tid);
        __syncthreads();
    }
    float acc[2][4][4];
#pragma unroll
    for (int mt = 0; mt < 2; mt++)
#pragma unroll
        for (int nt = 0; nt < 4; nt++)
#pragma unroll
            for (int r = 0; r < 4; r++) acc[mt][nt][r] = 0.f;

    for (int k0 = 0; k0 < K; k0 += 32) {
#pragma unroll
        for (int t = 0; t < 4; t++) {
            int li = tid + t * 256;
            int r = li >> 3, kq = li & 7;
            int row = r0 + r;
            float4 av = make_float4(0.f, 0.f, 0.f, 0.f);
            if (row < rows) {
                av = *(const float4*)(A + (size_t)row * lda + k0 + kq * 4);
                if (LNA) {
                    int b = g_abatch[row];
                    float mu = smu[b], rs = srs[b];
                    av.x = (av.x - mu) * rs; av.y = (av.y - mu) * rs;
                    av.z = (av.z - mu) * rs; av.w = (av.w - mu) * rs;
                }
            }
            bf_split4(av, &Ah[r][kq * 4], &Al[r][kq * 4]);
        }
#pragma unroll
        for (int t = 0; t < 2; t++) {
            int li = tid + t * 256;
            int kk = li >> 4, oq = li & 15;
            float4 wv = *(const float4*)(W + (size_t)(k0 + kk) * wld + col0 + oq * 4);
            __nv_bfloat16 hb[4], lb_[4];
            bf_split4(wv, hb, lb_);
#pragma unroll
            for (int jj = 0; jj < 4; jj++) { Wh[oq * 4 + jj][kk] = hb[jj]; Wl[oq * 4 + jj][kk] = lb_[jj]; }
        }
        __syncthreads();
#pragma unroll
        for (int ks = 0; ks < 2; ks++) {
            int kb = ks * 16;
            uint32_t ah[2][4], al[2][4];
#pragma unroll
            for (int mt = 0; mt < 2; mt++) {
                int ar = warpM * 32 + mt * 16 + gid;
                ah[mt][0] = *(const uint32_t*)&Ah[ar][kb + 2 * tig];
                ah[mt][1] = *(const uint32_t*)&Ah[ar + 8][kb + 2 * tig];
                ah[mt][2] = *(const uint32_t*)&Ah[ar][kb + 2 * tig + 8];
                ah[mt][3] = *(const uint32_t*)&Ah[ar + 8][kb + 2 * tig + 8];
                al[mt][0] = *(const uint32_t*)&Al[ar][kb + 2 * tig];
                al[mt][1] = *(const uint32_t*)&Al[ar + 8][kb + 2 * tig];
                al[mt][2] = *(const uint32_t*)&Al[ar][kb + 2 * tig + 8];
                al[mt][3] = *(const uint32_t*)&Al[ar + 8][kb + 2 * tig + 8];
            }
            uint32_t bh[4][2], bl[4][2];
#pragma unroll
            for (int nt = 0; nt < 4; nt++) {
                int bc = warpN * 32 + nt * 8 + gid;
                bh[nt][0] = *(const uint32_t*)&Wh[bc][kb + 2 * tig];
                bh[nt][1] = *(const uint32_t*)&Wh[bc][kb + 2 * tig + 8];
                bl[nt][0] = *(const uint32_t*)&Wl[bc][kb + 2 * tig];
                bl[nt][1] = *(const uint32_t*)&Wl[bc][kb + 2 * tig + 8];
            }
#pragma unroll
            for (int mt = 0; mt < 2; mt++)
#pragma unroll
                for (int nt = 0; nt < 4; nt++) {
                    mma16(acc[mt][nt], ah[mt][0], ah[mt][1], ah[mt][2], ah[mt][3],
                          bl[nt][0], bl[nt][1]);
                    mma16(acc[mt][nt], al[mt][0], al[mt][1], al[mt][2], al[mt][3],
                          bh[nt][0], bh[nt][1]);
                    mma16(acc[mt][nt], ah[mt][0], ah[mt][1], ah[mt][2], ah[mt][3],
                          bh[nt][0], bh[nt][1]);
                }
        }
        __syncthreads();
    }
#pragma unroll
    for (int mt = 0; mt < 2; mt++) {
        int rl = r0 + warpM * 32 + mt * 16 + gid;
#pragma unroll
        for (int half = 0; half < 2; half++) {
            int row = rl + half * 8;
            if (row >= rows) continue;
            float s = 0.f, ss = 0.f;
#pragma unroll
            for (int nt = 0; nt < 4; nt++) {
                int col = col0 + warpN * 32 + nt * 8 + tig * 2;
                float v0 = acc[mt][nt][half * 2 + 0];
                float v1 = acc[mt][nt][half * 2 + 1];
                v0 += bias[col]; v1 += bias[col + 1];
                if (ACT == 1) {
                    v0 = (v0 > 0.f) ? v0 : 0.01f * v0;
                    v1 = (v1 > 0.f) ? v1 : 0.01f * v1;
                }
                float2* cp = (float2*)(C + (size_t)row * ldc + col);
                if (ACCUM) { float2 o = *cp; v0 += o.x; v1 += o.y; }
                *cp = make_float2(v0, v1);
                if (STATS) { s += v0 + v1; ss += v0 * v0 + v1 * v1; }
            }
            if (STATS) {
                int rloc = row - r0;
                atomicAdd(&sS[rloc], s);
                atomicAdd(&sSS[rloc], ss);
            }
        }
    }
    if (STATS) {
        __syncthreads();
        if (tid < 128) {
            int row = r0 + tid;
            if (row < rows) {
                int b = g_abatch[row];
                atomicAdd(&oLs[b], (double)sS[tid]);
                atomicAdd(&oLss[b], (double)sSS[tid]);
            }
        }
    }
}

// ---------------- outputs ----------------
// also copies h -> out[0:NN*D64] (replaces the old memcpyAsync)
__global__ void k_out1(const int* __restrict__ batch, const int* __restrict__ ne0,
                       const int* __restrict__ ne1, float* __restrict__ out) {
    int idx = blockIdx.x * blockDim.x + threadIdx.x;
    if (idx < NN * D64) {
        float hv = g_h[idx];
        out[idx] = hv;
        atomicAdd(&g_gsum[batch[idx >> 6] * D64 + (idx & 63)], hv);
    }
    if (idx < NE_ * D64) {
        int j = idx >> 6, d = idx & 63;
        out[(NN + GG) * D64 + idx] = g_h[ne0[j] * D64 + d] + g_h[ne1[j] * D64 + d];
    }
}

__global__ void k_glob_out(float* __restrict__ out) {
    int idx = blockIdx.x * blockDim.x + threadIdx.x;
    if (idx >= GG * D64) return;
    int g = idx >> 6;
    out[NN * D64 + idx] = g_gsum[idx] / fmaxf(g_cntn[g], 1.f) + g_h[NN * D64 + idx];
}

__global__ void k_cleanup() {
    int idx = blockIdx.x * blockDim.x + threadIdx.x;
    if (idx < GG * D64) g_gsum[idx] = 0.f;
    if (idx < NSTAGE * GG) { g_lsum[idx] = 0.0; g_lsumsq[idx] = 0.0; }
    if (idx < GG) g_cntn[idx] = 0.f;
}

// ---------------- host launcher ----------------
#define GETSYM(ptr, sym) do { void* _p; cudaGetSymbolAddress(&_p, sym); ptr = (decltype(ptr))_p; } while (0)

extern "C" void kernel_launch(void* const* d_in, const int* in_sizes, int n_in,
                              void* d_out, int out_size) {
    const float* x          = (const float*)d_in[0];
    const float* cond       = (const float*)d_in[1];
    const float* edge_attr  = (const float*)d_in[2];
    const int*   edge_index = (const int*)d_in[3];
    const int*   ne_index   = (const int*)d_in[4];
    const int*   batch      = (const int*)d_in[5];
    const float* gen_w  = (const float*)d_in[6];
    const float* gen_b  = (const float*)d_in[7];
    const float* q_w    = (const float*)d_in[8];
    const float* q_b    = (const float*)d_in[9];
    const float* k_w    = (const float*)d_in[10];
    const float* k_b    = (const float*)d_in[11];
    const float* v_w    = (const float*)d_in[12];
    const float* v_b    = (const float*)d_in[13];
    const float* e_w    = (const float*)d_in[14];
    const float* skip_w = (const float*)d_in[15];
    const float* skip_b = (const float*)d_in[16];
    const float* lin_w  = (const float*)d_in[17];
    const float* lin_b  = (const float*)d_in[18];
    const float* ff_w1  = (const float*)d_in[19];
    const float* ff_b1  = (const float*)d_in[20];
    const float* ff_w2  = (const float*)d_in[21];
    const float* ff_b2  = (const float*)d_in[22];
    float* out = (float*)d_out;

    float *h_p, *big_p, *qkvp_p, *lh_p, *ffh_p;
    float *wcat2_p, *bcat2_p, *wlin2_p, *blb2_p;
    double *ls_p, *lss_p;
    GETSYM(h_p, g_h);       GETSYM(big_p, g_big);   GETSYM(qkvp_p, g_qkvp);
    GETSYM(lh_p, g_lh);     GETSYM(ffh_p, g_ffh);
    GETSYM(wcat2_p, g_wcat2); GETSYM(bcat2_p, g_bcat2);
    GETSYM(wlin2_p, g_wlin2); GETSYM(blb2_p, g_blb2);
    GETSYM(ls_p, g_lsum);   GETSYM(lss_p, g_lsumsq);

    const int T = 256;
    const int GRID_N = CDIV(NAUG, 128);
    cudaStream_t st = 0;

    // ---- setup (9 launches) ----
    k_build_edges<<<CDIV(MM, T), T, 0, st>>>(edge_index, edge_index + EE, batch);
    k_scanA<<<NB_SCAN, 256, 0, st>>>();
    k_scanB<<<1, 256, 0, st>>>();
    k_scanC<<<NB_SCAN, 256, 0, st>>>();
    k_scatter<<<CDIV(MM, T), T, 0, st>>>();
    k_misc<<<CDIV(NAUG * D64, T), T, 0, st>>>(x, cond, batch);
    k_eperm<<<CDIV(NAUG * 32, T), T, 0, st>>>(edge_attr);
    k_prep1<<<CDIV(LL * P1_PER, T), T, 0, st>>>(q_w, e_w, skip_w, lin_w, skip_b, lin_b);
    k_prep2<<<CDIV(LL * P2_PER, T), T, 0, st>>>(q_w, k_w, v_w, e_w, gen_w, gen_b,
                                                q_b, k_b, v_b, lin_w);

    // ---- layers (6 launches each) ----
    for (int i = 0; i < LL; i++) {
        const float* f1w = ff_w1 + (size_t)i * D64 * 4 * D64;
        const float* f1b = ff_b1 + (size_t)i * 4 * D64;
        const float* f2w = ff_w2 + (size_t)i * 4 * D64 * D64;
        const float* f2b = ff_b2 + (size_t)i * D64;
        float* wc2 = wcat2_p + (size_t)i * HD * 512;
        float* bc2 = bcat2_p + (size_t)i * 512;
        float* wl2 = wlin2_p + (size_t)i * 384 * D64;
        float* bl2 = blb2_p  + (size_t)i * D64;
        double* stLN1  = ls_p  + (size_t)(2 * i) * GG;
        double* stLN1s = lss_p + (size_t)(2 * i) * GG;
        double* stLN2  = ls_p  + (size_t)(2 * i + 1) * GG;
        double* stLN2s = lss_p + (size_t)(2 * i + 1) * GG;
        double* stNx   = ls_p  + (size_t)(2 * i + 2) * GG;
        double* stNxs  = lss_p + (size_t)(2 * i + 2) * GG;

        k_gen_all<<<NB_GEN + GG, T, 0, st>>>(h_p, stLN1, stLN1s);
        k_gemm_bf<0, 0, 0, 0><<<dim3(GRID_N, 8), T, 0, st>>>(
            big_p, 384, wc2, 512, bc2, qkvp_p, 512, NAUG, HD,
            nullptr, nullptr, nullptr, nullptr);
        k_attn_all<<<NB_GEN + GG, T, 0, st>>>();
        k_gemm_bf<0, 0, 0, 1><<<dim3(GRID_N, 1), T, 0, st>>>(
            big_p, 384, wl2, D64, bl2, lh_p, D64, NAUG, 384,
            nullptr, nullptr, stLN2, stLN2s);
        k_gemm_bf<1, 0, 1, 0><<<dim3(GRID_N, 4), T, 0, st>>>(
            lh_p, D64, f1w, 256, f1b, ffh_p, 256, NAUG, D64,
            stLN2, stLN2s, nullptr, nullptr);
        k_gemm_bf<0, 1, 0, 1><<<dim3(GRID_N, 1), T, 0, st>>>(
            ffh_p, 256, f2w, D64, f2b, h_p, D64, NAUG, 256,
            nullptr, nullptr, stNx, stNxs);
    }

    // ---- outputs ----
    k_out1<<<CDIV(NE_ * D64, T), T, 0, st>>>(batch, ne_index, ne_index + NE_, out);
    k_glob_out<<<CDIV(GG * D64, T), T, 0, st>>>(out);
    k_cleanup<<<CDIV(NSTAGE * GG, T) > CDIV(GG * D64, T) ? CDIV(NSTAGE * GG, T)
                                                         : CDIV(GG * D64, T), T, 0, st>>>();
}